// round 10
// baseline (speedup 1.0000x reference)
#include <cuda_runtime.h>
#include <cuda_fp16.h>
#include <cstdint>

#define NROWS   1152
#define OUT_CH  32
#define CTHREADS 384               // consumer: warps 0-11
#define THREADS  768               // + producer: warps 12-23
#define RPT     3                  // rows per consumer thread
#define ROWU32  16                 // 64B/row, chunk-XOR swizzled
#define LBATCH  8                  // front-batched LDG.128 per producer batch
#define NBATCH  3                  // 3 x 8 = 24 float4 per producer thread
#define LOG2E   1.4426950408889634f

// named barriers: FULL[b]=1,2 (prod arrive / cons sync), EMPTY[b]=3,4 (reverse),
// 5 = consumer-internal stage barrier
#define BARSYNC(id, n)   asm volatile("bar.sync %0, %1;"   :: "r"(id), "r"(n))
#define BARARRIVE(id, n) asm volatile("bar.arrive %0, %1;" :: "r"(id), "r"(n))

__device__ __forceinline__ float rcpa(float x) {
    float y; asm("rcp.approx.f32 %0, %1;" : "=f"(y) : "f"(x)); return y;
}
__device__ __forceinline__ unsigned ex2_h2(unsigned a) {
    unsigned y; asm("ex2.approx.f16x2 %0, %1;" : "=r"(y) : "r"(a)); return y;
}
__device__ __forceinline__ float warp_sum(float v) {
    v += __shfl_xor_sync(0xffffffffu, v, 16);
    v += __shfl_xor_sync(0xffffffffu, v, 8);
    v += __shfl_xor_sync(0xffffffffu, v, 4);
    v += __shfl_xor_sync(0xffffffffu, v, 2);
    v += __shfl_xor_sync(0xffffffffu, v, 1);
    return v;
}
__device__ __forceinline__ unsigned h2u(__half2 h)  { return *(unsigned*)&h; }
__device__ __forceinline__ __half2  u2h(unsigned u) { return *(__half2*)&u; }

// Persistent warp-specialized kernel: 1 CTA/SM, double-buffered fp16 tile.
// Producer warps stream sample j+1 with FRONT-BATCHED loads (8 LDG.128 in
// flight per warp) while consumer warps run routing sweeps on sample j.
__global__ __launch_bounds__(THREADS, 1)
void caps_kernel(const float* __restrict__ u_hat,
                 const float* __restrict__ cprior,
                 float* __restrict__ out,
                 int nsamp, int gridn)
{
    extern __shared__ unsigned smu[];
    unsigned* UB[2] = { smu, smu + NROWS * ROWU32 };          // 2 fp16 tiles
    float*    RED   = (float*)(smu + 2 * NROWS * ROWU32);    // [2][12][32] pass-0
    float*    CRED  = RED + 2 * 12 * OUT_CH;                 // [12][32] sweeps
    unsigned* V2    = (unsigned*)(CRED + 12 * OUT_CH);       // [16]

    const int tid = threadIdx.x;
    const int ns  = (nsamp - (int)blockIdx.x + gridn - 1) / gridn;

    if (tid >= CTHREADS) {
        // ---------------- producer: warps 12-23 ----------------
        const int pt   = tid - CTHREADS;
        const int lane = pt & 31;
        const int warp = pt >> 5;                  // 0..11
        const int cg   = (4 * pt) & 31;
        const float4 cj = __ldg((const float4*)(cprior + cg)); // row-uniform prior

        for (int j = 0; j < ns; j++) {
            const int b = j & 1;
            if (j >= 2) BARSYNC(3 + b, THREADS);   // buffer b free
            unsigned* U = UB[b];
            const size_t base =
                ((size_t)blockIdx.x + (size_t)gridn * j) * (NROWS * OUT_CH);
            float4 s0 = make_float4(0.f, 0.f, 0.f, 0.f);
#pragma unroll
            for (int kb = 0; kb < NBATCH; kb++) {
                // front-batched independent loads: 8 LDG.128 outstanding
                float4 ub[LBATCH];
#pragma unroll
                for (int q = 0; q < LBATCH; q++) {
                    const int e = (pt + CTHREADS * (kb * LBATCH + q)) << 2;
                    ub[q] = __ldg((const float4*)(u_hat + base + e));
                }
                // drain: dot + fp16 convert + swizzled STS
#pragma unroll
                for (int q = 0; q < LBATCH; q++) {
                    const int e   = (pt + CTHREADS * (kb * LBATCH + q)) << 2;
                    const int row = e >> 5;
                    const float4 u = ub[q];
                    s0.x = fmaf(u.x, cj.x, s0.x);
                    s0.y = fmaf(u.y, cj.y, s0.y);
                    s0.z = fmaf(u.z, cj.z, s0.z);
                    s0.w = fmaf(u.w, cj.w, s0.w);
                    const int chunk = (cg >> 3) ^ ((row >> 1) & 3);
                    unsigned* dst = U + row * ROWU32 + (chunk << 2)
                                    + ((cg & 4) >> 1);
                    *(uint2*)dst = make_uint2(h2u(__floats2half2_rn(u.x, u.y)),
                                              h2u(__floats2half2_rn(u.z, u.w)));
                }
            }
            // in-warp pass-0 reduce: lanes l, l+8, l+16, l+24 share group cg
            s0.x += __shfl_xor_sync(0xffffffffu, s0.x, 8);
            s0.y += __shfl_xor_sync(0xffffffffu, s0.y, 8);
            s0.z += __shfl_xor_sync(0xffffffffu, s0.z, 8);
            s0.w += __shfl_xor_sync(0xffffffffu, s0.w, 8);
            s0.x += __shfl_xor_sync(0xffffffffu, s0.x, 16);
            s0.y += __shfl_xor_sync(0xffffffffu, s0.y, 16);
            s0.z += __shfl_xor_sync(0xffffffffu, s0.z, 16);
            s0.w += __shfl_xor_sync(0xffffffffu, s0.w, 16);
            if (lane < 8)
                *(float4*)(RED + (b * 12 + warp) * OUT_CH + 4 * lane) = s0;
            __threadfence_block();                 // STS visible before arrive
            BARARRIVE(1 + b, THREADS);             // buffer b full
        }
    } else {
        // ---------------- consumer: warps 0-11 ----------------
        const int lane = tid & 31;
        const int warp = tid >> 5;

        for (int j = 0; j < ns; j++) {
            const int b = j & 1;
            BARSYNC(1 + b, THREADS);               // tile + RED[b] ready
            const unsigned* U = UB[b];

#pragma unroll 1
            for (int it = 0; it < 3; it++) {
                if (it > 0) BARSYNC(5, CTHREADS);  // CRED ready
                if (warp == 0) {
                    float t = 0.f;
                    const float* src = (it == 0) ? RED + b * 12 * OUT_CH : CRED;
#pragma unroll
                    for (int g = 0; g < 12; g++) t += src[g * OUT_CH + lane];
                    float n2 = warp_sum(t * t);
                    float v = n2 * rcpa(1.f + n2) * rsqrtf(n2 + 1e-8f) * t;
                    if (it == 2) {
                        out[((size_t)blockIdx.x + (size_t)gridn * j) * OUT_CH
                            + lane] = fmaf(0.5f, v, 0.5f);
                    } else {
                        float vl = v * LOG2E;
                        float a = __shfl_sync(0xffffffffu, vl, (2 * lane) & 31);
                        float bb = __shfl_sync(0xffffffffu, vl, (2 * lane + 1) & 31);
                        if (lane < 16) V2[lane] = h2u(__floats2half2_rn(a, bb));
                    }
                }
                if (it == 2) break;
                BARSYNC(5, CTHREADS);              // V2 ready, CRED reads done

                unsigned sp2[16];
#pragma unroll
                for (int p = 0; p < 16; p++) sp2[p] = 0u;
                const volatile unsigned* v2s = V2;
#pragma unroll
                for (int k = 0; k < RPT; k++) {
                    const int rr = tid + CTHREADS * k;
                    const unsigned* rbase = U + rr * ROWU32;
                    const int sw = (rr >> 1) & 3;
                    unsigned up[16];
#pragma unroll
                    for (int q = 0; q < 4; q++) {
                        uint4 w = *(const uint4*)(rbase + ((q ^ sw) << 2));
                        up[4*q+0] = w.x; up[4*q+1] = w.y;
                        up[4*q+2] = w.z; up[4*q+3] = w.w;
                    }
                    __half2 d2[4];
#pragma unroll
                    for (int p = 0; p < 4; p++) d2[p] = __floats2half2_rn(0.f, 0.f);
#pragma unroll
                    for (int p = 0; p < 16; p++) {
                        unsigned a  = h2u(__hmul2(u2h(up[p]), u2h(v2s[p])));
                        unsigned e2 = ex2_h2(a);
                        d2[p & 3]   = __hadd2(d2[p & 3], u2h(e2));
                        up[p]       = h2u(__hmul2(u2h(up[p]), u2h(e2)));
                    }
                    __half2 dd = __hadd2(__hadd2(d2[0], d2[1]),
                                         __hadd2(d2[2], d2[3]));
                    float2 df = __half22float2(dd);
                    const __half2 r2 = __float2half2_rn(rcpa(df.x + df.y));
#pragma unroll
                    for (int p = 0; p < 16; p++)
                        sp2[p] = h2u(__hfma2(u2h(up[p]), r2, u2h(sp2[p])));
                }
                // widen once; exact fp32 in-register warp transpose-reduce
                float sp[OUT_CH];
#pragma unroll
                for (int p = 0; p < 16; p++) {
                    float2 f = __half22float2(u2h(sp2[p]));
                    sp[2 * p] = f.x; sp[2 * p + 1] = f.y;
                }
#pragma unroll
                for (int m = 16; m >= 1; m >>= 1) {
#pragma unroll
                    for (int k2 = 0; k2 < m; k2++) {
                        float send = (lane & m) ? sp[k2] : sp[k2 + m];
                        float recv = __shfl_xor_sync(0xffffffffu, send, m);
                        sp[k2] = ((lane & m) ? sp[k2 + m] : sp[k2]) + recv;
                    }
                }
                CRED[warp * OUT_CH + lane] = sp[0];
            }
            BARARRIVE(3 + b, THREADS);             // buffer b free
        }
    }
}

extern "C" void kernel_launch(void* const* d_in, const int* in_sizes, int n_in,
                              void* d_out, int out_size)
{
    const float* u_hat = (const float*)d_in[0];
    const float* c     = (const float*)d_in[1];
    const int n = in_sizes[0] / (NROWS * OUT_CH);      // 4096
    int sms = 148;
    cudaDeviceGetAttribute(&sms, cudaDevAttrMultiProcessorCount, 0);
    if (sms > n) sms = n;
    const int smem = (2 * NROWS * ROWU32) * 4
                   + (2 * 12 * OUT_CH + 12 * OUT_CH) * 4 + 64;   // ~149 KB
    cudaFuncSetAttribute(caps_kernel,
                         cudaFuncAttributeMaxDynamicSharedMemorySize, smem);
    caps_kernel<<<sms, THREADS, smem>>>(u_hat, c, (float*)d_out, n, sms);
}

// round 11
// speedup vs baseline: 1.1672x; 1.1672x over previous
#include <cuda_runtime.h>
#include <cuda_fp16.h>
#include <cstdint>

#define NROWS   1152
#define OUT_CH  32
#define THREADS 768                // 24 warps; 2 CTAs/SM -> 48 warps
#define NWARP   24
#define HRPT    3                  // half-rows per thread (2304/768)
#define ROWU32  16                 // 64B/row, chunk-XOR swizzled
#define F4PT    12                 // float4 gmem loads per thread
#define LOG2E   1.4426950408889634f

__device__ __forceinline__ float rcpa(float x) {
    float y; asm("rcp.approx.f32 %0, %1;" : "=f"(y) : "f"(x)); return y;
}
__device__ __forceinline__ unsigned ex2_h2(unsigned a) {
    unsigned y; asm("ex2.approx.f16x2 %0, %1;" : "=r"(y) : "r"(a)); return y;
}
__device__ __forceinline__ float warp_sum(float v) {
    v += __shfl_xor_sync(0xffffffffu, v, 16);
    v += __shfl_xor_sync(0xffffffffu, v, 8);
    v += __shfl_xor_sync(0xffffffffu, v, 4);
    v += __shfl_xor_sync(0xffffffffu, v, 2);
    v += __shfl_xor_sync(0xffffffffu, v, 1);
    return v;
}
__device__ __forceinline__ unsigned h2u(__half2 h)  { return *(unsigned*)&h; }
__device__ __forceinline__ __half2  u2h(unsigned u) { return *(__half2*)&u; }

// One CTA per sample, 2 CTAs/SM (48 warps). Each thread owns 3 HALF-rows
// (16 channels, parity-fixed): short dependency chains, small register set,
// one shfl per row for the softmax denominator.
__global__ __launch_bounds__(THREADS, 2)
void caps_kernel(const float* __restrict__ u_hat,
                 const float* __restrict__ cprior,
                 float* __restrict__ out)
{
    extern __shared__ unsigned smu[];
    unsigned* U   = smu;                            // [1152][16] u32 (half2)
    float*    RED = (float*)(smu + NROWS * ROWU32); // [24][32] (pass-0 & sweeps)
    unsigned* V2  = (unsigned*)(RED + NWARP * OUT_CH); // [16] packed v*log2e

    const int tid  = threadIdx.x;
    const int lane = tid & 31;
    const int warp = tid >> 5;
    const int par  = tid & 1;                       // half parity (channels 16*par..)
    const size_t base = (size_t)blockIdx.x * (NROWS * OUT_CH);

    // ---- coalesced fp32 load, fused exact pass-0 dot, swizzled fp16 store ----
    const int cg = (4 * tid) & 31;
    const float4 cj = __ldg((const float4*)(cprior + cg));  // row-uniform prior
    float4 s0 = make_float4(0.f, 0.f, 0.f, 0.f);
#pragma unroll
    for (int k = 0; k < F4PT; k++) {
        const int e   = (tid + THREADS * k) << 2;
        const int row = e >> 5;
        const float4 u = __ldg((const float4*)(u_hat + base + e));
        s0.x = fmaf(u.x, cj.x, s0.x);
        s0.y = fmaf(u.y, cj.y, s0.y);
        s0.z = fmaf(u.z, cj.z, s0.z);
        s0.w = fmaf(u.w, cj.w, s0.w);
        const int chunk = (cg >> 3) ^ ((row >> 1) & 3);
        unsigned* dst = U + row * ROWU32 + (chunk << 2) + ((cg & 4) >> 1);
        *(uint2*)dst = make_uint2(h2u(__floats2half2_rn(u.x, u.y)),
                                  h2u(__floats2half2_rn(u.z, u.w)));
    }
    // in-warp pass-0 reduce: lanes l, l+8, l+16, l+24 share channel group cg
    s0.x += __shfl_xor_sync(0xffffffffu, s0.x, 8);
    s0.y += __shfl_xor_sync(0xffffffffu, s0.y, 8);
    s0.z += __shfl_xor_sync(0xffffffffu, s0.z, 8);
    s0.w += __shfl_xor_sync(0xffffffffu, s0.w, 8);
    s0.x += __shfl_xor_sync(0xffffffffu, s0.x, 16);
    s0.y += __shfl_xor_sync(0xffffffffu, s0.y, 16);
    s0.z += __shfl_xor_sync(0xffffffffu, s0.z, 16);
    s0.w += __shfl_xor_sync(0xffffffffu, s0.w, 16);
    if (lane < 8)
        *(float4*)(RED + warp * OUT_CH + 4 * lane) = s0;

    // ---- 3 squash stages; stages 0,1 followed by an exp/softmax sweep ----
#pragma unroll 1
    for (int it = 0; it < 3; it++) {
        __syncthreads();                            // RED ready
        if (warp == 0) {
            float t = 0.f;
#pragma unroll
            for (int g = 0; g < NWARP; g++) t += RED[g * OUT_CH + lane];
            float n2 = warp_sum(t * t);
            float v = n2 * rcpa(1.f + n2) * rsqrtf(n2 + 1e-8f) * t;
            if (it == 2) {
                out[(size_t)blockIdx.x * OUT_CH + lane] = fmaf(0.5f, v, 0.5f);
            } else {
                float vl = v * LOG2E;
                float a = __shfl_sync(0xffffffffu, vl, (2 * lane) & 31);
                float b = __shfl_sync(0xffffffffu, vl, (2 * lane + 1) & 31);
                if (lane < 16) V2[lane] = h2u(__floats2half2_rn(a, b));
            }
        }
        if (it == 2) break;
        __syncthreads();                            // V2 ready, RED reads done

        // hot sweep: each thread = 3 half-rows (16 channels), parity-fixed
        unsigned sp2[8];
#pragma unroll
        for (int p = 0; p < 8; p++) sp2[p] = 0u;
        const volatile unsigned* v2s = V2 + 8 * par;

#pragma unroll
        for (int k = 0; k < HRPT; k++) {
            const int hh  = tid + THREADS * k;      // half-row index
            const int row = hh >> 1;                // hh&1 == par (768 even)
            const unsigned* rbase = U + row * ROWU32;
            const int sw = (row >> 1) & 3;
            const int h0 = 2 * par;                 // logical chunks h0, h0+1
            uint4 w0 = *(const uint4*)(rbase + (((h0)     ^ sw) << 2));
            uint4 w1 = *(const uint4*)(rbase + (((h0 + 1) ^ sw) << 2));
            unsigned up[8] = { w0.x, w0.y, w0.z, w0.w, w1.x, w1.y, w1.z, w1.w };

            __half2 da = __floats2half2_rn(0.f, 0.f);
            __half2 db = __floats2half2_rn(0.f, 0.f);
#pragma unroll
            for (int p = 0; p < 8; p++) {
                unsigned a  = h2u(__hmul2(u2h(up[p]), u2h(v2s[p]))); // u*v*log2e
                unsigned e2 = ex2_h2(a);                             // exp x2
                if (p & 1) db = __hadd2(db, u2h(e2));
                else       da = __hadd2(da, u2h(e2));
                up[p] = h2u(__hmul2(u2h(up[p]), u2h(e2)));           // u*exp
            }
            float2 df = __half22float2(__hadd2(da, db));
            float dloc = df.x + df.y;                    // my 16 channels
            float drow = dloc + __shfl_xor_sync(0xffffffffu, dloc, 1); // +partner
            const __half2 r2 = __float2half2_rn(rcpa(drow));  // 1 rcp per row-half
#pragma unroll
            for (int p = 0; p < 8; p++)
                sp2[p] = h2u(__hfma2(u2h(up[p]), r2, u2h(sp2[p])));
        }

        // cross-lane reduce (same-parity lanes hold disjoint channel halves):
        // 1 packed fp16 level (xor16), then fp32 levels (xor8,4,2).
        // Result: lane l holds channel 16*(l&1) + (l>>1).
        unsigned q[8];
#pragma unroll
        for (int p = 0; p < 8; p++) q[p] = sp2[p];
#pragma unroll
        for (int k2 = 0; k2 < 4; k2++) {            // xor16, offset 4
            unsigned send = (lane & 16) ? q[k2] : q[k2 + 4];
            unsigned recv = __shfl_xor_sync(0xffffffffu, send, 16);
            q[k2] = h2u(__hadd2(u2h((lane & 16) ? q[k2 + 4] : q[k2]), u2h(recv)));
        }
        float f[8];
#pragma unroll
        for (int k2 = 0; k2 < 4; k2++) {            // unpack to fp32
            float2 t2 = __half22float2(u2h(q[k2]));
            f[2 * k2] = t2.x; f[2 * k2 + 1] = t2.y;
        }
#pragma unroll
        for (int k2 = 0; k2 < 4; k2++) {            // xor8, offset 4
            float send = (lane & 8) ? f[k2] : f[k2 + 4];
            float recv = __shfl_xor_sync(0xffffffffu, send, 8);
            f[k2] = ((lane & 8) ? f[k2 + 4] : f[k2]) + recv;
        }
#pragma unroll
        for (int k2 = 0; k2 < 2; k2++) {            // xor4, offset 2
            float send = (lane & 4) ? f[k2] : f[k2 + 2];
            float recv = __shfl_xor_sync(0xffffffffu, send, 4);
            f[k2] = ((lane & 4) ? f[k2 + 2] : f[k2]) + recv;
        }
        {                                            // xor2, offset 1
            float send = (lane & 2) ? f[0] : f[1];
            float recv = __shfl_xor_sync(0xffffffffu, send, 2);
            f[0] = ((lane & 2) ? f[1] : f[0]) + recv;
        }
        __syncthreads();                             // V2/RED readers done
        RED[warp * OUT_CH + 16 * (lane & 1) + ((lane >> 1) & 15)] = f[0];
    }
}

extern "C" void kernel_launch(void* const* d_in, const int* in_sizes, int n_in,
                              void* d_out, int out_size)
{
    const float* u_hat = (const float*)d_in[0];
    const float* c     = (const float*)d_in[1];
    const int n = in_sizes[0] / (NROWS * OUT_CH);      // 4096
    const int smem = (NROWS * ROWU32 + NWARP * OUT_CH + 16) * 4;  // ~76.9 KB
    cudaFuncSetAttribute(caps_kernel,
                         cudaFuncAttributeMaxDynamicSharedMemorySize, smem);
    caps_kernel<<<n, THREADS, smem>>>(u_hat, c, (float*)d_out);
}

// round 12
// speedup vs baseline: 1.1840x; 1.0144x over previous
#include <cuda_runtime.h>
#include <cuda_fp16.h>
#include <cstdint>

#define NROWS   1152
#define OUT_CH  32
#define THREADS 768                // 24 warps; 2 CTAs/SM -> 48 warps
#define NWARP   24
#define HRPT    3                  // half-rows per thread (2304/768)
#define ROWU32  16                 // 64B/row, chunk-XOR swizzled
#define F4PT    12                 // float4 gmem loads per thread
#define LOG2E   1.4426950408889634f

__device__ __forceinline__ float rcpa(float x) {
    float y; asm("rcp.approx.f32 %0, %1;" : "=f"(y) : "f"(x)); return y;
}
__device__ __forceinline__ unsigned ex2_h2(unsigned a) {
    unsigned y; asm("ex2.approx.f16x2 %0, %1;" : "=r"(y) : "r"(a)); return y;
}
__device__ __forceinline__ float warp_sum(float v) {
    v += __shfl_xor_sync(0xffffffffu, v, 16);
    v += __shfl_xor_sync(0xffffffffu, v, 8);
    v += __shfl_xor_sync(0xffffffffu, v, 4);
    v += __shfl_xor_sync(0xffffffffu, v, 2);
    v += __shfl_xor_sync(0xffffffffu, v, 1);
    return v;
}
__device__ __forceinline__ unsigned h2u(__half2 h)  { return *(unsigned*)&h; }
__device__ __forceinline__ __half2  u2h(unsigned u) { return *(__half2*)&u; }

// One CTA per sample, 2 CTAs/SM (48 warps). Each thread owns 3 HALF-rows
// (16 channels, parity-fixed). v is cached in 8 registers per sweep instead
// of re-read from smem per element group (the R11 volatile-LDS tax).
__global__ __launch_bounds__(THREADS, 2)
void caps_kernel(const float* __restrict__ u_hat,
                 const float* __restrict__ cprior,
                 float* __restrict__ out)
{
    extern __shared__ unsigned smu[];
    unsigned* U   = smu;                            // [1152][16] u32 (half2)
    float*    RED = (float*)(smu + NROWS * ROWU32); // [24][32] (pass-0 & sweeps)
    unsigned* V2  = (unsigned*)(RED + NWARP * OUT_CH); // [16] packed v*log2e

    const int tid  = threadIdx.x;
    const int lane = tid & 31;
    const int warp = tid >> 5;
    const int par  = tid & 1;                       // half parity
    const size_t base = (size_t)blockIdx.x * (NROWS * OUT_CH);

    // ---- coalesced fp32 load, fused exact pass-0 dot, swizzled fp16 store ----
    const int cg = (4 * tid) & 31;
    const float4 cj = __ldg((const float4*)(cprior + cg));  // row-uniform prior
    float4 s0 = make_float4(0.f, 0.f, 0.f, 0.f);
#pragma unroll
    for (int k = 0; k < F4PT; k++) {
        const int e   = (tid + THREADS * k) << 2;
        const int row = e >> 5;
        const float4 u = __ldg((const float4*)(u_hat + base + e));
        s0.x = fmaf(u.x, cj.x, s0.x);
        s0.y = fmaf(u.y, cj.y, s0.y);
        s0.z = fmaf(u.z, cj.z, s0.z);
        s0.w = fmaf(u.w, cj.w, s0.w);
        const int chunk = (cg >> 3) ^ ((row >> 1) & 3);
        unsigned* dst = U + row * ROWU32 + (chunk << 2) + ((cg & 4) >> 1);
        *(uint2*)dst = make_uint2(h2u(__floats2half2_rn(u.x, u.y)),
                                  h2u(__floats2half2_rn(u.z, u.w)));
    }
    // in-warp pass-0 reduce: lanes l, l+8, l+16, l+24 share channel group cg
    s0.x += __shfl_xor_sync(0xffffffffu, s0.x, 8);
    s0.y += __shfl_xor_sync(0xffffffffu, s0.y, 8);
    s0.z += __shfl_xor_sync(0xffffffffu, s0.z, 8);
    s0.w += __shfl_xor_sync(0xffffffffu, s0.w, 8);
    s0.x += __shfl_xor_sync(0xffffffffu, s0.x, 16);
    s0.y += __shfl_xor_sync(0xffffffffu, s0.y, 16);
    s0.z += __shfl_xor_sync(0xffffffffu, s0.z, 16);
    s0.w += __shfl_xor_sync(0xffffffffu, s0.w, 16);
    if (lane < 8)
        *(float4*)(RED + warp * OUT_CH + 4 * lane) = s0;

    // ---- 3 squash stages; stages 0,1 followed by an exp/softmax sweep ----
#pragma unroll 1
    for (int it = 0; it < 3; it++) {
        __syncthreads();                            // RED ready
        if (warp == 0) {
            float t = 0.f;
#pragma unroll
            for (int g = 0; g < NWARP; g++) t += RED[g * OUT_CH + lane];
            float n2 = warp_sum(t * t);
            float v = n2 * rcpa(1.f + n2) * rsqrtf(n2 + 1e-8f) * t;
            if (it == 2) {
                out[(size_t)blockIdx.x * OUT_CH + lane] = fmaf(0.5f, v, 0.5f);
            } else {
                float vl = v * LOG2E;
                float a = __shfl_sync(0xffffffffu, vl, (2 * lane) & 31);
                float b = __shfl_sync(0xffffffffu, vl, (2 * lane + 1) & 31);
                if (lane < 16) V2[lane] = h2u(__floats2half2_rn(a, b));
            }
        }
        if (it == 2) break;
        __syncthreads();                            // V2 ready, RED reads done

        // cache my 8 packed v-pairs in registers for the whole sweep
        unsigned v2loc[8];
#pragma unroll
        for (int p = 0; p < 8; p++) v2loc[p] = V2[8 * par + p];

        // hot sweep: each thread = 3 half-rows (16 channels), parity-fixed
        unsigned sp2[8];
#pragma unroll
        for (int p = 0; p < 8; p++) sp2[p] = 0u;

#pragma unroll
        for (int k = 0; k < HRPT; k++) {
            const int hh  = tid + THREADS * k;      // half-row index
            const int row = hh >> 1;                // hh&1 == par (768 even)
            const unsigned* rbase = U + row * ROWU32;
            const int sw = (row >> 1) & 3;
            const int h0 = 2 * par;                 // logical chunks h0, h0+1
            uint4 w0 = *(const uint4*)(rbase + (((h0)     ^ sw) << 2));
            uint4 w1 = *(const uint4*)(rbase + (((h0 + 1) ^ sw) << 2));
            unsigned up[8] = { w0.x, w0.y, w0.z, w0.w, w1.x, w1.y, w1.z, w1.w };

            __half2 da = __floats2half2_rn(0.f, 0.f);
            __half2 db = __floats2half2_rn(0.f, 0.f);
#pragma unroll
            for (int p = 0; p < 8; p++) {
                unsigned a  = h2u(__hmul2(u2h(up[p]), u2h(v2loc[p]))); // u*v*log2e
                unsigned e2 = ex2_h2(a);                               // exp x2
                if (p & 1) db = __hadd2(db, u2h(e2));
                else       da = __hadd2(da, u2h(e2));
                up[p] = h2u(__hmul2(u2h(up[p]), u2h(e2)));             // u*exp
            }
            float2 df = __half22float2(__hadd2(da, db));
            float dloc = df.x + df.y;                    // my 16 channels
            float drow = dloc + __shfl_xor_sync(0xffffffffu, dloc, 1); // +partner
            const __half2 r2 = __float2half2_rn(rcpa(drow));  // 1 rcp per half-row
#pragma unroll
            for (int p = 0; p < 8; p++)
                sp2[p] = h2u(__hfma2(u2h(up[p]), r2, u2h(sp2[p])));
        }

        // cross-lane reduce (same-parity lanes hold disjoint channel halves):
        // 1 packed fp16 level (xor16), then fp32 levels (xor8,4,2).
#pragma unroll
        for (int k2 = 0; k2 < 4; k2++) {            // xor16, packed
            unsigned send = (lane & 16) ? sp2[k2] : sp2[k2 + 4];
            unsigned recv = __shfl_xor_sync(0xffffffffu, send, 16);
            sp2[k2] = h2u(__hadd2(u2h((lane & 16) ? sp2[k2 + 4] : sp2[k2]),
                                  u2h(recv)));
        }
        float f[8];
#pragma unroll
        for (int k2 = 0; k2 < 4; k2++) {            // unpack to fp32
            float2 t2 = __half22float2(u2h(sp2[k2]));
            f[2 * k2] = t2.x; f[2 * k2 + 1] = t2.y;
        }
#pragma unroll
        for (int k2 = 0; k2 < 4; k2++) {            // xor8
            float send = (lane & 8) ? f[k2] : f[k2 + 4];
            float recv = __shfl_xor_sync(0xffffffffu, send, 8);
            f[k2] = ((lane & 8) ? f[k2 + 4] : f[k2]) + recv;
        }
#pragma unroll
        for (int k2 = 0; k2 < 2; k2++) {            // xor4
            float send = (lane & 4) ? f[k2] : f[k2 + 2];
            float recv = __shfl_xor_sync(0xffffffffu, send, 4);
            f[k2] = ((lane & 4) ? f[k2 + 2] : f[k2]) + recv;
        }
        {                                            // xor2
            float send = (lane & 2) ? f[0] : f[1];
            float recv = __shfl_xor_sync(0xffffffffu, send, 2);
            f[0] = ((lane & 2) ? f[1] : f[0]) + recv;
        }
        __syncthreads();                             // V2/RED readers done
        RED[warp * OUT_CH + 16 * (lane & 1) + ((lane >> 1) & 15)] = f[0];
    }
}

extern "C" void kernel_launch(void* const* d_in, const int* in_sizes, int n_in,
                              void* d_out, int out_size)
{
    const float* u_hat = (const float*)d_in[0];
    const float* c     = (const float*)d_in[1];
    const int n = in_sizes[0] / (NROWS * OUT_CH);      // 4096
    const int smem = (NROWS * ROWU32 + NWARP * OUT_CH + 16) * 4;  // ~76.9 KB
    cudaFuncSetAttribute(caps_kernel,
                         cudaFuncAttributeMaxDynamicSharedMemorySize, smem);
    caps_kernel<<<n, THREADS, smem>>>(u_hat, c, (float*)d_out);
}